// round 2
// baseline (speedup 1.0000x reference)
#include <cuda_runtime.h>
#include <cuda_bf16.h>

// GAT: 4 GATConv layers (3 heads x 12 out), concat for layers 0-2 (relu), mean
// for layer 3, then two small linear layers -> [N, 6].
//
// Strategy:
//  1) Build CSR by destination ONCE per launch (self-loops folded in).
//  2) Per layer: node transform (h = yW^T + attn logits), then warp-per-node
//     softmax aggregation in registers (max-subtraction dropped: exact, since
//     every segment has a self-loop and logits are O(1)).
//  3) Fused lin1+lin2 -> d_out.

#define HEADS 3
#define OUTF  12
#define F     36            // HEADS*OUTF
#define NMAX  50000
#define EMAX  800000
#define TOTMAX (EMAX + NMAX)

// ---------------- device scratch (static; no allocation) ----------------
__device__ float g_y[NMAX * F];     // layer activations (holds [N,12] after layer 3)
__device__ float g_h[NMAX * F];     // transformed features for current layer
__device__ float g_als[NMAX * HEADS];
__device__ float g_ald[NMAX * HEADS];
__device__ int   g_deg[NMAX];
__device__ int   g_rowstart[NMAX + 1];
__device__ int   g_cursor[NMAX];
__device__ int   g_csrsrc[TOTMAX];
__device__ int   g_blocksums[128];
__device__ int   g_blockoffs[128];

// ---------------- CSR build ----------------
__global__ void k_init_deg(int N) {
    int i = blockIdx.x * blockDim.x + threadIdx.x;
    if (i < N) g_deg[i] = 1;  // self-loop
}

__global__ void k_hist(const int* __restrict__ dst, int E) {
    int e = blockIdx.x * blockDim.x + threadIdx.x;
    if (e < E) atomicAdd(&g_deg[dst[e]], 1);
}

__global__ void k_scan_block(int N) {  // blockDim == 1024
    __shared__ int sh[1024];
    int t = threadIdx.x;
    int idx = blockIdx.x * 1024 + t;
    int v = (idx < N) ? g_deg[idx] : 0;
    sh[t] = v;
    __syncthreads();
    #pragma unroll
    for (int off = 1; off < 1024; off <<= 1) {
        int add = (t >= off) ? sh[t - off] : 0;
        __syncthreads();
        sh[t] += add;
        __syncthreads();
    }
    if (idx < N) g_rowstart[idx] = sh[t];          // per-block inclusive (temp)
    if (t == 1023) g_blocksums[blockIdx.x] = sh[1023];
}

__global__ void k_scan_sums(int nb) {  // single block, 128 threads
    __shared__ int sh[128];
    int t = threadIdx.x;
    int own = (t < nb) ? g_blocksums[t] : 0;
    sh[t] = own;
    __syncthreads();
    #pragma unroll
    for (int off = 1; off < 128; off <<= 1) {
        int add = (t >= off) ? sh[t - off] : 0;
        __syncthreads();
        sh[t] += add;
        __syncthreads();
    }
    g_blockoffs[t] = sh[t] - own;  // exclusive block offset
}

__global__ void k_scan_finish(int N, int TOT) {
    int idx = blockIdx.x * blockDim.x + threadIdx.x;
    if (idx < N) {
        int incl = g_rowstart[idx] + g_blockoffs[idx >> 10];
        int ex = incl - g_deg[idx];
        g_rowstart[idx] = ex;
        g_cursor[idx] = ex;
    }
    if (idx == 0) g_rowstart[N] = TOT;
}

__global__ void k_scatter(const int* __restrict__ src, const int* __restrict__ dst,
                          int E, int N) {
    int i = blockIdx.x * blockDim.x + threadIdx.x;
    if (i < E) {
        int d = dst[i];
        int pos = atomicAdd(&g_cursor[d], 1);
        g_csrsrc[pos] = src[i];
    } else if (i < E + N) {
        int n = i - E;
        int pos = atomicAdd(&g_cursor[n], 1);
        g_csrsrc[pos] = n;  // self loop
    }
}

// ---------------- node transform: h = y @ W^T, attention logits ----------------
template <int IN, bool FROMX>
__global__ void k_node_transform(const float* __restrict__ xin,
                                 const float* __restrict__ W,
                                 const float* __restrict__ asrc,
                                 const float* __restrict__ adst, int N) {
    __shared__ float sW[F * F];
    __shared__ float sA[F], sB[F];
    int t = threadIdx.x;
    for (int i = t; i < F * IN; i += blockDim.x) sW[i] = W[i];
    if (t < F) { sA[t] = asrc[t]; sB[t] = adst[t]; }
    __syncthreads();
    int n = blockIdx.x * blockDim.x + t;
    if (n >= N) return;

    const float* yrow = FROMX ? (xin + (size_t)n * IN) : (g_y + (size_t)n * F);
    float yr[IN];
    #pragma unroll
    for (int i = 0; i < IN; i++) yr[i] = yrow[i];

    float h[F];
    #pragma unroll
    for (int j = 0; j < F; j++) {
        float acc = 0.f;
        #pragma unroll
        for (int i = 0; i < IN; i++) acc += sW[j * IN + i] * yr[i];
        h[j] = acc;
        g_h[(size_t)n * F + j] = acc;
    }
    #pragma unroll
    for (int hh = 0; hh < HEADS; hh++) {
        float as = 0.f, ad = 0.f;
        #pragma unroll
        for (int o = 0; o < OUTF; o++) {
            as += h[hh * OUTF + o] * sA[hh * OUTF + o];
            ad += h[hh * OUTF + o] * sB[hh * OUTF + o];
        }
        g_als[n * HEADS + hh] = as;
        g_ald[n * HEADS + hh] = ad;
    }
}

// ---------------- aggregation: one warp per destination node ----------------
template <bool CONCAT>
__global__ void k_gat_aggregate(const float* __restrict__ bias, int N) {
    int warp = (blockIdx.x * blockDim.x + threadIdx.x) >> 5;
    int lane = threadIdx.x & 31;
    if (warp >= N) return;
    int n = warp;
    int r0 = g_rowstart[n];
    int r1 = g_rowstart[n + 1];
    float ald0 = g_ald[n * 3 + 0];
    float ald1 = g_ald[n * 3 + 1];
    float ald2 = g_ald[n * 3 + 2];

    float s0 = 0.f, s1 = 0.f, s2 = 0.f;
    float acc[F];
    #pragma unroll
    for (int f = 0; f < F; f++) acc[f] = 0.f;

    for (int i = r0 + lane; i < r1; i += 32) {
        int src = g_csrsrc[i];
        float e0 = g_als[src * 3 + 0] + ald0;
        float e1 = g_als[src * 3 + 1] + ald1;
        float e2 = g_als[src * 3 + 2] + ald2;
        e0 = (e0 > 0.f) ? e0 : 0.2f * e0;
        e1 = (e1 > 0.f) ? e1 : 0.2f * e1;
        e2 = (e2 > 0.f) ? e2 : 0.2f * e2;
        float p0 = __expf(e0), p1 = __expf(e1), p2 = __expf(e2);
        s0 += p0; s1 += p1; s2 += p2;
        const float4* hr = (const float4*)(g_h + (size_t)src * F);
        #pragma unroll
        for (int q = 0; q < 9; q++) {
            float4 v = hr[q];
            float p = (q < 3) ? p0 : ((q < 6) ? p1 : p2);
            acc[q * 4 + 0] += p * v.x;
            acc[q * 4 + 1] += p * v.y;
            acc[q * 4 + 2] += p * v.z;
            acc[q * 4 + 3] += p * v.w;
        }
    }

    // butterfly reduce (all lanes end with full sums)
    #pragma unroll
    for (int off = 16; off; off >>= 1) {
        s0 += __shfl_xor_sync(0xFFFFFFFFu, s0, off);
        s1 += __shfl_xor_sync(0xFFFFFFFFu, s1, off);
        s2 += __shfl_xor_sync(0xFFFFFFFFu, s2, off);
        #pragma unroll
        for (int f = 0; f < F; f++)
            acc[f] += __shfl_xor_sync(0xFFFFFFFFu, acc[f], off);
    }

    float inv0 = 1.f / (s0 + 1e-16f);
    float inv1 = 1.f / (s1 + 1e-16f);
    float inv2 = 1.f / (s2 + 1e-16f);

    if (CONCAT) {
        {
            int j = lane;  // 0..31
            float inv = (j < 12) ? inv0 : ((j < 24) ? inv1 : inv2);
            float v = acc[j] * inv + bias[j];
            g_y[(size_t)n * F + j] = fmaxf(v, 0.f);
        }
        if (lane < 4) {
            int j = 32 + lane;  // head 2
            float v = acc[j] * inv2 + bias[j];
            g_y[(size_t)n * F + j] = fmaxf(v, 0.f);
        }
    } else {
        if (lane < OUTF) {
            float v = (acc[lane] * inv0 + acc[12 + lane] * inv1 +
                       acc[24 + lane] * inv2) * (1.f / 3.f) + bias[lane];
            g_y[(size_t)n * OUTF + lane] = v;  // no relu on last GAT layer
        }
    }
}

// ---------------- final linears: [N,12] -> 12 -> 6 ----------------
__global__ void k_final_linear(const float* __restrict__ w1, const float* __restrict__ b1,
                               const float* __restrict__ w2, const float* __restrict__ b2,
                               float* __restrict__ out, int N) {
    __shared__ float sw1[144], sb1[12], sw2[72], sb2[6];
    int t = threadIdx.x;
    for (int i = t; i < 144; i += blockDim.x) sw1[i] = w1[i];
    for (int i = t; i < 72;  i += blockDim.x) sw2[i] = w2[i];
    if (t < 12) sb1[t] = b1[t];
    if (t < 6)  sb2[t] = b2[t];
    __syncthreads();
    int n = blockIdx.x * blockDim.x + t;
    if (n >= N) return;
    float v[12];
    #pragma unroll
    for (int i = 0; i < 12; i++) v[i] = g_y[(size_t)n * 12 + i];
    float u[12];
    #pragma unroll
    for (int j = 0; j < 12; j++) {
        float a = sb1[j];
        #pragma unroll
        for (int i = 0; i < 12; i++) a += v[i] * sw1[j * 12 + i];
        u[j] = a;
    }
    #pragma unroll
    for (int k = 0; k < 6; k++) {
        float a = sb2[k];
        #pragma unroll
        for (int j = 0; j < 12; j++) a += u[j] * sw2[k * 12 + j];
        out[(size_t)n * 6 + k] = a;
    }
}

// ---------------- launch ----------------
extern "C" void kernel_launch(void* const* d_in, const int* in_sizes, int n_in,
                              void* d_out, int out_size) {
    const float* x  = (const float*)d_in[0];
    const int*   ei = (const int*)d_in[1];
    int E = in_sizes[1] / 2;
    int N = in_sizes[0] / 24;
    if (N > NMAX || E > EMAX) return;
    const int* srcp = ei;
    const int* dstp = ei + E;

    const float* W[4], *AS[4], *AD[4], *B[4];
    for (int l = 0; l < 4; l++) {
        W[l]  = (const float*)d_in[2 + 4 * l];
        AS[l] = (const float*)d_in[3 + 4 * l];
        AD[l] = (const float*)d_in[4 + 4 * l];
        B[l]  = (const float*)d_in[5 + 4 * l];
    }
    const float* lin1w = (const float*)d_in[18];
    const float* lin1b = (const float*)d_in[19];
    const float* lin2w = (const float*)d_in[20];
    const float* lin2b = (const float*)d_in[21];
    float* out = (float*)d_out;

    int TOT = E + N;
    int nb = (N + 1023) / 1024;

    k_init_deg<<<(N + 255) / 256, 256>>>(N);
    k_hist<<<(E + 255) / 256, 256>>>(dstp, E);
    k_scan_block<<<nb, 1024>>>(N);
    k_scan_sums<<<1, 128>>>(nb);
    k_scan_finish<<<(N + 255) / 256, 256>>>(N, TOT);
    k_scatter<<<(TOT + 255) / 256, 256>>>(srcp, dstp, E, N);

    int tb = 128;
    int ngrid = (N + tb - 1) / tb;
    int agrid = (N * 32 + 255) / 256;

    // layer 0 (in=24, from x)
    k_node_transform<24, true><<<ngrid, tb>>>(x, W[0], AS[0], AD[0], N);
    k_gat_aggregate<true><<<agrid, 256>>>(B[0], N);
    // layer 1
    k_node_transform<36, false><<<ngrid, tb>>>(nullptr, W[1], AS[1], AD[1], N);
    k_gat_aggregate<true><<<agrid, 256>>>(B[1], N);
    // layer 2
    k_node_transform<36, false><<<ngrid, tb>>>(nullptr, W[2], AS[2], AD[2], N);
    k_gat_aggregate<true><<<agrid, 256>>>(B[2], N);
    // layer 3 (mean over heads, no relu)
    k_node_transform<36, false><<<ngrid, tb>>>(nullptr, W[3], AS[3], AD[3], N);
    k_gat_aggregate<false><<<agrid, 256>>>(B[3], N);

    k_final_linear<<<ngrid, tb>>>(lin1w, lin1b, lin2w, lin2b, out, N);
}

// round 4
// speedup vs baseline: 2.2940x; 2.2940x over previous
#include <cuda_runtime.h>
#include <cuda_bf16.h>

// GAT: 4 GATConv layers (3 heads x 12 out), concat for layers 0-2 (relu), mean
// for layer 3, then two small linear layers -> [N, 6].
//
//  1) Build CSR by destination ONCE per launch (self-loops folded in).
//  2) Per layer: node transform (smem-staged, coalesced), then aggregation with
//     FEATURE-PER-LANE warps: lane f owns feature f, walks edges serially with
//     coalesced h-row gathers; softmax denominator is accumulated identically
//     by all lanes of a head group (no reduction needed). Max-subtraction is
//     dropped: exact since all segments contain a self-loop and logits are O(1).
//  3) Fused lin1+lin2 -> d_out.

#define HEADS 3
#define OUTF  12
#define F     36            // HEADS*OUTF
#define NMAX  50000
#define EMAX  800000
#define TOTMAX (EMAX + NMAX)

// ---------------- device scratch (static; no allocation) ----------------
__device__ float g_y[NMAX * F];     // layer activations (holds [N,12] after layer 3)
__device__ float g_h[NMAX * F];     // transformed features for current layer
__device__ float g_als[NMAX * HEADS];
__device__ float g_ald[NMAX * HEADS];
__device__ int   g_deg[NMAX];
__device__ int   g_rowstart[NMAX + 1];
__device__ int   g_cursor[NMAX];
__device__ int   g_csrsrc[TOTMAX + 32];   // +32 pad for chunked over-read
__device__ int   g_blocksums[128];
__device__ int   g_blockoffs[128];

// ---------------- CSR build ----------------
__global__ void k_init_deg(int N) {
    int i = blockIdx.x * blockDim.x + threadIdx.x;
    if (i < N) g_deg[i] = 1;  // self-loop
}

__global__ void k_hist(const int* __restrict__ dst, int E) {
    int e = blockIdx.x * blockDim.x + threadIdx.x;
    if (e < E) atomicAdd(&g_deg[dst[e]], 1);
}

__global__ void k_scan_block(int N) {  // blockDim == 1024
    __shared__ int sh[1024];
    int t = threadIdx.x;
    int idx = blockIdx.x * 1024 + t;
    int v = (idx < N) ? g_deg[idx] : 0;
    sh[t] = v;
    __syncthreads();
    #pragma unroll
    for (int off = 1; off < 1024; off <<= 1) {
        int add = (t >= off) ? sh[t - off] : 0;
        __syncthreads();
        sh[t] += add;
        __syncthreads();
    }
    if (idx < N) g_rowstart[idx] = sh[t];          // per-block inclusive (temp)
    if (t == 1023) g_blocksums[blockIdx.x] = sh[1023];
}

__global__ void k_scan_sums(int nb) {  // single block, 128 threads
    __shared__ int sh[128];
    int t = threadIdx.x;
    int own = (t < nb) ? g_blocksums[t] : 0;
    sh[t] = own;
    __syncthreads();
    #pragma unroll
    for (int off = 1; off < 128; off <<= 1) {
        int add = (t >= off) ? sh[t - off] : 0;
        __syncthreads();
        sh[t] += add;
        __syncthreads();
    }
    g_blockoffs[t] = sh[t] - own;  // exclusive block offset
}

__global__ void k_scan_finish(int N, int TOT) {
    int idx = blockIdx.x * blockDim.x + threadIdx.x;
    if (idx < N) {
        int incl = g_rowstart[idx] + g_blockoffs[idx >> 10];
        int ex = incl - g_deg[idx];
        g_rowstart[idx] = ex;
        g_cursor[idx] = ex;
    }
    if (idx == 0) g_rowstart[N] = TOT;
}

__global__ void k_scatter(const int* __restrict__ src, const int* __restrict__ dst,
                          int E, int N) {
    int i = blockIdx.x * blockDim.x + threadIdx.x;
    if (i < E) {
        int d = dst[i];
        int pos = atomicAdd(&g_cursor[d], 1);
        g_csrsrc[pos] = src[i];
    } else if (i < E + N) {
        int n = i - E;
        int pos = atomicAdd(&g_cursor[n], 1);
        g_csrsrc[pos] = n;  // self loop
    }
}

// ---------------- node transform: h = y @ W^T, attention logits ----------------
// Block = 128 threads = 128 nodes. Input rows staged coalesced into padded
// smem (stride 37: odd -> bank-conflict-free row reads); h staged back through
// the same buffer and stored coalesced.
template <int IN, bool FROMX>
__global__ void __launch_bounds__(128) k_node_transform(
        const float* __restrict__ xin,
        const float* __restrict__ W,
        const float* __restrict__ asrc,
        const float* __restrict__ adst, int N) {
    __shared__ float sW[F * F];
    __shared__ float sA[F], sB[F];
    __shared__ float sy[128 * 37];
    int t = threadIdx.x;
    for (int i = t; i < F * IN; i += 128) sW[i] = W[i];
    if (t < F) { sA[t] = asrc[t]; sB[t] = adst[t]; }

    int n0 = blockIdx.x * 128;
    int rows = min(128, N - n0);
    const float* srcbase = FROMX ? (xin + (size_t)n0 * IN) : (g_y + (size_t)n0 * IN);
    int avail = rows * IN;
    for (int idx = t; idx < avail; idx += 128) {
        int r = idx / IN, c = idx - r * IN;
        sy[r * 37 + c] = srcbase[idx];
    }
    __syncthreads();

    int n = n0 + t;
    float h[F];
    if (t < rows) {
        float yr[IN];
        #pragma unroll
        for (int i = 0; i < IN; i++) yr[i] = sy[t * 37 + i];
        #pragma unroll
        for (int j = 0; j < F; j++) {
            float acc = 0.f;
            #pragma unroll
            for (int i = 0; i < IN; i++) acc += sW[j * IN + i] * yr[i];
            h[j] = acc;
        }
        #pragma unroll
        for (int hh = 0; hh < HEADS; hh++) {
            float as = 0.f, ad = 0.f;
            #pragma unroll
            for (int o = 0; o < OUTF; o++) {
                as += h[hh * OUTF + o] * sA[hh * OUTF + o];
                ad += h[hh * OUTF + o] * sB[hh * OUTF + o];
            }
            g_als[n * HEADS + hh] = as;
            g_ald[n * HEADS + hh] = ad;
        }
    }
    __syncthreads();  // all reads of sy done
    if (t < rows) {
        #pragma unroll
        for (int j = 0; j < F; j++) sy[t * 37 + j] = h[j];
    }
    __syncthreads();
    int availh = rows * F;
    float* hbase = g_h + (size_t)n0 * F;
    for (int idx = t; idx < availh; idx += 128) {
        int r = idx / F, c = idx - r * F;
        hbase[idx] = sy[r * 37 + c];
    }
}

// ---------------- aggregation: warp per node, FEATURE per lane ----------------
// Lane f accumulates output feature f (lanes 0..3 also own features 32..35).
// All lanes walk every edge of the node: p for a lane's head is computed from a
// broadcast als load; the h gather is a coalesced 128B row read. The softmax
// denominator sp is accumulated identically by every lane of a head group, so
// no cross-lane reduction is ever needed.
template <bool CONCAT>
__global__ void k_gat_aggregate(const float* __restrict__ bias, int N) {
    int warp = (blockIdx.x * blockDim.x + threadIdx.x) >> 5;
    int lane = threadIdx.x & 31;
    if (warp >= N) return;
    int n = warp;
    int r0 = g_rowstart[n];
    int r1 = g_rowstart[n + 1];

    int f1 = lane;                 // feature 0..31
    int h1 = lane / OUTF;          // head of f1
    float ald1 = g_ald[n * 3 + h1];

    float acc1 = 0.f, acc2 = 0.f, sp1 = 0.f, sp2 = 0.f;

    for (int base = r0; base < r1; base += 32) {
        int mysrc = g_csrsrc[base + lane];   // chunk preload (padded tail)
        int cnt = min(32, r1 - base);
        #pragma unroll 4
        for (int j = 0; j < cnt; j++) {
            int s = __shfl_sync(0xFFFFFFFFu, mysrc, j);
            float e1 = g_als[s * 3 + h1] + ald1;
            e1 = (e1 > 0.f) ? e1 : 0.2f * e1;
            float p1 = __expf(e1);
            // head-2 p for the second-feature lanes, taken from lane 24
            float p2 = __shfl_sync(0xFFFFFFFFu, p1, 24);
            sp1 += p1;
            acc1 += p1 * g_h[(size_t)s * F + f1];
            if (lane < 4) {
                sp2 += p2;
                acc2 += p2 * g_h[(size_t)s * F + 32 + lane];
            }
        }
    }

    float inv1 = 1.f / (sp1 + 1e-16f);

    if (CONCAT) {
        float v = acc1 * inv1 + bias[f1];
        g_y[(size_t)n * F + f1] = fmaxf(v, 0.f);
        if (lane < 4) {
            float inv2 = 1.f / (sp2 + 1e-16f);
            float v2 = acc2 * inv2 + bias[32 + lane];
            g_y[(size_t)n * F + 32 + lane] = fmaxf(v2, 0.f);
        }
    } else {
        // mean over heads. Normalized per-lane value:
        float v1 = acc1 * inv1;                       // (head h1, feat f1%12)
        float inv2 = 1.f / (sp2 + 1e-16f);
        float v2 = acc2 * inv2;                       // lanes 0..3: head2 feats 8..11
        // out feature o (o = lane < 12): head0 from lane o, head1 from lane o+12,
        // head2 from lane o+24 (o<8) or v2 of lane o-8 (o>=8).
        float b12 = __shfl_sync(0xFFFFFFFFu, v1, lane + 12);
        float c24 = __shfl_sync(0xFFFFFFFFu, v1, lane + 24);
        float c2  = __shfl_sync(0xFFFFFFFFu, v2, lane - 8);
        if (lane < OUTF) {
            float c = (lane < 8) ? c24 : c2;
            float v = (v1 + b12 + c) * (1.f / 3.f) + bias[lane];
            g_y[(size_t)n * OUTF + lane] = v;   // no relu on last GAT layer
        }
    }
}

// ---------------- final linears: [N,12] -> 12 -> 6 ----------------
__global__ void k_final_linear(const float* __restrict__ w1, const float* __restrict__ b1,
                               const float* __restrict__ w2, const float* __restrict__ b2,
                               float* __restrict__ out, int N) {
    __shared__ float sw1[144], sb1[12], sw2[72], sb2[6];
    int t = threadIdx.x;
    for (int i = t; i < 144; i += blockDim.x) sw1[i] = w1[i];
    for (int i = t; i < 72;  i += blockDim.x) sw2[i] = w2[i];
    if (t < 12) sb1[t] = b1[t];
    if (t < 6)  sb2[t] = b2[t];
    __syncthreads();
    int n = blockIdx.x * blockDim.x + t;
    if (n >= N) return;
    float v[12];
    const float4* vp = (const float4*)(g_y + (size_t)n * 12);
    #pragma unroll
    for (int q = 0; q < 3; q++) {
        float4 w = vp[q];
        v[q * 4 + 0] = w.x; v[q * 4 + 1] = w.y;
        v[q * 4 + 2] = w.z; v[q * 4 + 3] = w.w;
    }
    float u[12];
    #pragma unroll
    for (int j = 0; j < 12; j++) {
        float a = sb1[j];
        #pragma unroll
        for (int i = 0; i < 12; i++) a += v[i] * sw1[j * 12 + i];
        u[j] = a;
    }
    #pragma unroll
    for (int k = 0; k < 6; k++) {
        float a = sb2[k];
        #pragma unroll
        for (int j = 0; j < 12; j++) a += u[j] * sw2[k * 12 + j];
        out[(size_t)n * 6 + k] = a;
    }
}

// ---------------- launch ----------------
extern "C" void kernel_launch(void* const* d_in, const int* in_sizes, int n_in,
                              void* d_out, int out_size) {
    const float* x  = (const float*)d_in[0];
    const int*   ei = (const int*)d_in[1];
    int E = in_sizes[1] / 2;
    int N = in_sizes[0] / 24;
    if (N > NMAX || E > EMAX) return;
    const int* srcp = ei;
    const int* dstp = ei + E;

    const float* W[4], *AS[4], *AD[4], *B[4];
    for (int l = 0; l < 4; l++) {
        W[l]  = (const float*)d_in[2 + 4 * l];
        AS[l] = (const float*)d_in[3 + 4 * l];
        AD[l] = (const float*)d_in[4 + 4 * l];
        B[l]  = (const float*)d_in[5 + 4 * l];
    }
    const float* lin1w = (const float*)d_in[18];
    const float* lin1b = (const float*)d_in[19];
    const float* lin2w = (const float*)d_in[20];
    const float* lin2b = (const float*)d_in[21];
    float* out = (float*)d_out;

    int TOT = E + N;
    int nb = (N + 1023) / 1024;

    k_init_deg<<<(N + 255) / 256, 256>>>(N);
    k_hist<<<(E + 255) / 256, 256>>>(dstp, E);
    k_scan_block<<<nb, 1024>>>(N);
    k_scan_sums<<<1, 128>>>(nb);
    k_scan_finish<<<(N + 255) / 256, 256>>>(N, TOT);
    k_scatter<<<(TOT + 255) / 256, 256>>>(srcp, dstp, E, N);

    int ngrid = (N + 127) / 128;
    int agrid = (N * 32 + 255) / 256;

    // layer 0 (in=24, from x)
    k_node_transform<24, true><<<ngrid, 128>>>(x, W[0], AS[0], AD[0], N);
    k_gat_aggregate<true><<<agrid, 256>>>(B[0], N);
    // layer 1
    k_node_transform<36, false><<<ngrid, 128>>>(nullptr, W[1], AS[1], AD[1], N);
    k_gat_aggregate<true><<<agrid, 256>>>(B[1], N);
    // layer 2
    k_node_transform<36, false><<<ngrid, 128>>>(nullptr, W[2], AS[2], AD[2], N);
    k_gat_aggregate<true><<<agrid, 256>>>(B[2], N);
    // layer 3 (mean over heads, no relu)
    k_node_transform<36, false><<<ngrid, 128>>>(nullptr, W[3], AS[3], AD[3], N);
    k_gat_aggregate<false><<<agrid, 256>>>(B[3], N);

    k_final_linear<<<(N + 127) / 128, 128>>>(lin1w, lin1b, lin2w, lin2b, out, N);
}

// round 6
// speedup vs baseline: 2.3572x; 1.0275x over previous
#include <cuda_runtime.h>
#include <cuda_bf16.h>

// GAT: 4 GATConv layers (3 heads x 12 out), concat for layers 0-2 (relu), mean
// for layer 3, then two small linear layers -> [N, 6].
//
//  1) Build CSR by destination ONCE per launch (4 kernels: hist, scan_block,
//     scan_finish (fused block-sum scan + deg reset for next graph replay),
//     scatter). Self-loops folded in as deg+1 during the scan.
//  2) Per layer: node transform (smem-staged, 2-node register blocking), then
//     aggregation with FEATURE-PER-LANE warps; second features 32..35 owned by
//     lanes 24..27 (head-2 lanes) so their own p/sp are reused -> no per-edge
//     shuffle. Softmax max-subtraction dropped: exact since all segments have
//     a self-loop and logits are O(1).
//  3) Fused lin1+lin2 -> d_out.

#define HEADS 3
#define OUTF  12
#define F     36            // HEADS*OUTF
#define NMAX  50000
#define EMAX  800000
#define TOTMAX (EMAX + NMAX)

// ---------------- device scratch (static; no allocation) ----------------
__device__ float g_y[NMAX * F];     // layer activations (holds [N,12] after layer 3)
__device__ float g_h[NMAX * F];     // transformed features for current layer
__device__ float g_als[NMAX * HEADS];
__device__ float g_ald[NMAX * HEADS];
__device__ int   g_deg[NMAX];       // zero at entry (zero-init / reset each pass)
__device__ int   g_rowstart[NMAX + 1];
__device__ int   g_cursor[NMAX];
__device__ int   g_csrsrc[TOTMAX + 32];   // +32 pad (zero-init) for chunked over-read
__device__ int   g_blocksums[128];

// ---------------- CSR build ----------------
__global__ void k_hist(const int* __restrict__ dst, int E) {
    int e = blockIdx.x * blockDim.x + threadIdx.x;
    if (e < E) atomicAdd(&g_deg[dst[e]], 1);
}

__global__ void k_scan_block(int N) {  // blockDim == 1024
    __shared__ int sh[1024];
    int t = threadIdx.x;
    int idx = blockIdx.x * 1024 + t;
    int v = (idx < N) ? (g_deg[idx] + 1) : 0;   // +1 = self-loop
    sh[t] = v;
    __syncthreads();
    #pragma unroll
    for (int off = 1; off < 1024; off <<= 1) {
        int add = (t >= off) ? sh[t - off] : 0;
        __syncthreads();
        sh[t] += add;
        __syncthreads();
    }
    if (idx < N) g_rowstart[idx] = sh[t];          // per-block inclusive (temp)
    if (t == 1023) g_blocksums[blockIdx.x] = sh[1023];
}

// Fused: every block scans the (<=128) block sums redundantly in smem, then
// converts to exclusive row starts, initializes cursors, and RESETS g_deg so
// the next graph replay starts from zero.
__global__ void k_scan_finish(int N, int TOT, int nb) {
    __shared__ int soff[128];
    int t = threadIdx.x;    // blockDim == 256
    if (t < 128) soff[t] = (t < nb) ? g_blocksums[t] : 0;
    __syncthreads();
    #pragma unroll
    for (int off = 1; off < 128; off <<= 1) {
        int add = 0;
        if (t < 128 && t >= off) add = soff[t - off];
        __syncthreads();
        if (t < 128) soff[t] += add;
        __syncthreads();
    }
    int idx = blockIdx.x * blockDim.x + t;
    if (idx < N) {
        int b = idx >> 10;
        int boff = (b == 0) ? 0 : soff[b - 1];
        int incl = g_rowstart[idx] + boff;
        int ex = incl - (g_deg[idx] + 1);
        g_rowstart[idx] = ex;
        g_cursor[idx] = ex;
        g_deg[idx] = 0;       // reset for next replay
    }
    if (idx == 0) g_rowstart[N] = TOT;
}

__global__ void k_scatter(const int* __restrict__ src, const int* __restrict__ dst,
                          int E, int N) {
    int i = blockIdx.x * blockDim.x + threadIdx.x;
    if (i < E) {
        int d = dst[i];
        int pos = atomicAdd(&g_cursor[d], 1);
        g_csrsrc[pos] = src[i];
    } else if (i < E + N) {
        int n = i - E;
        int pos = atomicAdd(&g_cursor[n], 1);
        g_csrsrc[pos] = n;  // self loop
    }
}

// ---------------- node transform: h = y @ W^T, attention logits ----------------
// Block = 128 threads handling 256 nodes (2 per thread): halves the broadcast
// LDS traffic for sW. Rows staged coalesced into padded smem (stride 37, odd
// -> conflict-free); h written back into the same rows and stored coalesced.
template <int IN, bool FROMX>
__global__ void __launch_bounds__(128) k_node_transform(
        const float* __restrict__ xin,
        const float* __restrict__ W,
        const float* __restrict__ asrc,
        const float* __restrict__ adst, int N) {
    __shared__ float sW[F * F];
    __shared__ float sA[F], sB[F];
    __shared__ float sy[256 * 37];
    int t = threadIdx.x;
    for (int i = t; i < F * IN; i += 128) sW[i] = W[i];
    if (t < F) { sA[t] = asrc[t]; sB[t] = adst[t]; }

    int n0 = blockIdx.x * 256;
    int rows = min(256, N - n0);
    const float* srcbase = FROMX ? (xin + (size_t)n0 * IN) : (g_y + (size_t)n0 * IN);
    int avail = rows * IN;
    for (int idx = t; idx < avail; idx += 128) {
        int r = idx / IN, c = idx - r * IN;
        sy[r * 37 + c] = srcbase[idx];
    }
    __syncthreads();

    bool va = (t < rows);
    bool vb = (t + 128 < rows);
    int na = n0 + t, nb2 = n0 + t + 128;
    float ya[IN], yb[IN];
    #pragma unroll
    for (int i = 0; i < IN; i++) ya[i] = va ? sy[t * 37 + i] : 0.f;
    #pragma unroll
    for (int i = 0; i < IN; i++) yb[i] = vb ? sy[(t + 128) * 37 + i] : 0.f;

    float asa[3] = {0.f, 0.f, 0.f}, ada[3] = {0.f, 0.f, 0.f};
    float asb[3] = {0.f, 0.f, 0.f}, adb[3] = {0.f, 0.f, 0.f};

    #pragma unroll
    for (int j = 0; j < F; j++) {
        float ha = 0.f, hb = 0.f;
        #pragma unroll
        for (int i = 0; i < IN; i++) {
            float w = sW[j * IN + i];
            ha += w * ya[i];
            hb += w * yb[i];
        }
        sy[t * 37 + j] = ha;            // own row: no cross-thread hazard
        sy[(t + 128) * 37 + j] = hb;
        float aj = sA[j], bj = sB[j];
        int hh = j / OUTF;
        asa[hh] += ha * aj; ada[hh] += ha * bj;
        asb[hh] += hb * aj; adb[hh] += hb * bj;
    }
    if (va) {
        #pragma unroll
        for (int hh = 0; hh < 3; hh++) {
            g_als[na * 3 + hh] = asa[hh];
            g_ald[na * 3 + hh] = ada[hh];
        }
    }
    if (vb) {
        #pragma unroll
        for (int hh = 0; hh < 3; hh++) {
            g_als[nb2 * 3 + hh] = asb[hh];
            g_ald[nb2 * 3 + hh] = adb[hh];
        }
    }
    __syncthreads();
    int availh = rows * F;
    float* hbase = g_h + (size_t)n0 * F;
    for (int idx = t; idx < availh; idx += 128) {
        int r = idx / F, c = idx - r * F;
        hbase[idx] = sy[r * 37 + c];
    }
}

// ---------------- aggregation: warp per node, FEATURE per lane ----------------
// Lane f (0..31) owns feature f; lanes 24..27 additionally own features 32..35
// (same head 2 -> reuse own p and sp; no shuffle needed). All lanes walk every
// edge; the softmax denominator is accumulated identically by every lane of a
// head group, so no cross-lane reduction is ever needed.
template <bool CONCAT>
__global__ void k_gat_aggregate(const float* __restrict__ bias, int N) {
    int warp = (blockIdx.x * blockDim.x + threadIdx.x) >> 5;
    int lane = threadIdx.x & 31;
    if (warp >= N) return;
    int n = warp;
    int r0 = g_rowstart[n];
    int r1 = g_rowstart[n + 1];

    int h1 = lane / OUTF;          // 0,1,2
    float ald1 = g_ald[n * 3 + h1];
    bool sec = (lane >= 24) && (lane < 28);

    float acc1 = 0.f, acc2 = 0.f, sp1 = 0.f;

    for (int base = r0; base < r1; base += 32) {
        int mysrc = g_csrsrc[base + lane];   // chunk preload (zero-init padded tail)
        int cnt = min(32, r1 - base);
        #pragma unroll 4
        for (int j = 0; j < cnt; j++) {
            int s = __shfl_sync(0xFFFFFFFFu, mysrc, j);
            float e = g_als[s * 3 + h1] + ald1;
            e = fmaxf(e, 0.2f * e);          // leaky relu (slope < 1)
            float p = __expf(e);
            sp1 += p;
            const float* hr = g_h + (size_t)s * F;
            acc1 += p * hr[lane];
            if (sec) acc2 += p * hr[32 + (lane - 24)];
        }
    }

    float inv1 = 1.f / (sp1 + 1e-16f);

    if (CONCAT) {
        float v = acc1 * inv1 + bias[lane];
        g_y[(size_t)n * F + lane] = fmaxf(v, 0.f);
        if (sec) {
            float v2 = acc2 * inv1 + bias[32 + (lane - 24)];
            g_y[(size_t)n * F + 32 + (lane - 24)] = fmaxf(v2, 0.f);
        }
    } else {
        // mean over heads
        float v1 = acc1 * inv1;              // (head h1, feat lane%12)
        float v2 = acc2 * inv1;              // lanes 24..27: head2 feats 8..11
        float b12 = __shfl_sync(0xFFFFFFFFu, v1, lane + 12);           // head1
        float c24 = __shfl_sync(0xFFFFFFFFu, v1, lane + 24);           // head2 o<8
        float c2  = __shfl_sync(0xFFFFFFFFu, v2, lane + 16);           // head2 o>=8
        if (lane < OUTF) {
            float c = (lane < 8) ? c24 : c2;
            float v = (v1 + b12 + c) * (1.f / 3.f) + bias[lane];
            g_y[(size_t)n * OUTF + lane] = v;   // no relu on last GAT layer
        }
    }
}

// ---------------- final linears: [N,12] -> 12 -> 6 ----------------
__global__ void k_final_linear(const float* __restrict__ w1, const float* __restrict__ b1,
                               const float* __restrict__ w2, const float* __restrict__ b2,
                               float* __restrict__ out, int N) {
    __shared__ float sw1[144], sb1[12], sw2[72], sb2[6];
    int t = threadIdx.x;
    for (int i = t; i < 144; i += blockDim.x) sw1[i] = w1[i];
    for (int i = t; i < 72;  i += blockDim.x) sw2[i] = w2[i];
    if (t < 12) sb1[t] = b1[t];
    if (t < 6)  sb2[t] = b2[t];
    __syncthreads();
    int n = blockIdx.x * blockDim.x + t;
    if (n >= N) return;
    float v[12];
    const float4* vp = (const float4*)(g_y + (size_t)n * 12);
    #pragma unroll
    for (int q = 0; q < 3; q++) {
        float4 w = vp[q];
        v[q * 4 + 0] = w.x; v[q * 4 + 1] = w.y;
        v[q * 4 + 2] = w.z; v[q * 4 + 3] = w.w;
    }
    float u[12];
    #pragma unroll
    for (int j = 0; j < 12; j++) {
        float a = sb1[j];
        #pragma unroll
        for (int i = 0; i < 12; i++) a += v[i] * sw1[j * 12 + i];
        u[j] = a;
    }
    #pragma unroll
    for (int k = 0; k < 6; k++) {
        float a = sb2[k];
        #pragma unroll
        for (int j = 0; j < 12; j++) a += u[j] * sw2[k * 12 + j];
        out[(size_t)n * 6 + k] = a;
    }
}

// ---------------- launch ----------------
extern "C" void kernel_launch(void* const* d_in, const int* in_sizes, int n_in,
                              void* d_out, int out_size) {
    const float* x  = (const float*)d_in[0];
    const int*   ei = (const int*)d_in[1];
    int E = in_sizes[1] / 2;
    int N = in_sizes[0] / 24;
    if (N > NMAX || E > EMAX) return;
    const int* srcp = ei;
    const int* dstp = ei + E;

    const float* W[4], *AS[4], *AD[4], *B[4];
    for (int l = 0; l < 4; l++) {
        W[l]  = (const float*)d_in[2 + 4 * l];
        AS[l] = (const float*)d_in[3 + 4 * l];
        AD[l] = (const float*)d_in[4 + 4 * l];
        B[l]  = (const float*)d_in[5 + 4 * l];
    }
    const float* lin1w = (const float*)d_in[18];
    const float* lin1b = (const float*)d_in[19];
    const float* lin2w = (const float*)d_in[20];
    const float* lin2b = (const float*)d_in[21];
    float* out = (float*)d_out;

    int TOT = E + N;
    int nb = (N + 1023) / 1024;

    k_hist<<<(E + 255) / 256, 256>>>(dstp, E);
    k_scan_block<<<nb, 1024>>>(N);
    k_scan_finish<<<(N + 255) / 256, 256>>>(N, TOT, nb);
    k_scatter<<<(TOT + 255) / 256, 256>>>(srcp, dstp, E, N);

    int ngrid = (N + 255) / 256;     // 256 nodes per transform block
    int agrid = (N * 32 + 255) / 256;

    // layer 0 (in=24, from x)
    k_node_transform<24, true><<<ngrid, 128>>>(x, W[0], AS[0], AD[0], N);
    k_gat_aggregate<true><<<agrid, 256>>>(B[0], N);
    // layer 1
    k_node_transform<36, false><<<ngrid, 128>>>(nullptr, W[1], AS[1], AD[1], N);
    k_gat_aggregate<true><<<agrid, 256>>>(B[1], N);
    // layer 2
    k_node_transform<36, false><<<ngrid, 128>>>(nullptr, W[2], AS[2], AD[2], N);
    k_gat_aggregate<true><<<agrid, 256>>>(B[2], N);
    // layer 3 (mean over heads, no relu)
    k_node_transform<36, false><<<ngrid, 128>>>(nullptr, W[3], AS[3], AD[3], N);
    k_gat_aggregate<false><<<agrid, 256>>>(B[3], N);

    k_final_linear<<<(N + 127) / 128, 128>>>(lin1w, lin1b, lin2w, lin2b, out, N);
}